// round 1
// baseline (speedup 1.0000x reference)
#include <cuda_runtime.h>
#include <math.h>

#define N_   16
#define CIN  192
#define CB_  64
#define HH   100
#define WW   100
#define HWS  10000

// Max branch (nw=12, k=12): 16*64*(12*12)^2 = 21,233,664 elems
#define MAXEL (16*64*20736)

__device__ float g_xc [N_*CB_*HWS];     // conv1 output (16,64,100,100)
__device__ float g_u4 [MAXEL];          // patch buffer, linear (n,c,i,j,wy,wx)
__device__ float g_y  [MAXEL];          // conv2 output (u4-view layout)
__device__ float g_a  [MAXEL];          // se*y + dwconv + bpos
__device__ float g_cat[N_*CIN*HWS];     // folded concat (16,192,100,100)
__device__ float g_mean [2304*64];
__device__ float g_scale[2304*64];

// ---------------- conv1: x(16,192,100,100) @ w1(64,192) -> g_xc ----------------
__global__ __launch_bounds__(256) void conv1_k(const float* __restrict__ x,
                                               const float* __restrict__ w1,
                                               const float* __restrict__ b1) {
    __shared__ float wT[16][64];
    __shared__ float inT[16][128];
    int n = blockIdx.y;
    int hw0 = blockIdx.x * 128;
    int tx = threadIdx.x;
    int og = tx >> 5, pg = tx & 31;
    int ob = og * 8, pb = pg * 4;
    float acc[8][4];
#pragma unroll
    for (int i = 0; i < 8; i++)
#pragma unroll
        for (int j = 0; j < 4; j++) acc[i][j] = 0.f;

    for (int c0 = 0; c0 < 192; c0 += 16) {
#pragma unroll
        for (int r = 0; r < 4; r++) {
            int e = tx + r * 256;
            wT[e >> 6][e & 63] = w1[(e & 63) * 192 + c0 + (e >> 6)];
        }
#pragma unroll
        for (int r = 0; r < 8; r++) {
            int e = tx + r * 256;
            int cc = e >> 7, pp = e & 127;
            int hw = hw0 + pp;
            inT[cc][pp] = (hw < HWS) ? x[((size_t)n * CIN + c0 + cc) * HWS + hw] : 0.f;
        }
        __syncthreads();
#pragma unroll
        for (int cc = 0; cc < 16; cc++) {
            float4 iv = *(const float4*)&inT[cc][pb];
#pragma unroll
            for (int q = 0; q < 8; q++) {
                float wv = wT[cc][ob + q];
                acc[q][0] += wv * iv.x; acc[q][1] += wv * iv.y;
                acc[q][2] += wv * iv.z; acc[q][3] += wv * iv.w;
            }
        }
        __syncthreads();
    }
    if (hw0 + pb < HWS) {
#pragma unroll
        for (int q = 0; q < 8; q++) {
            int o = ob + q;
            float bv = b1[o];
            float4 v = make_float4(acc[q][0] + bv, acc[q][1] + bv,
                                   acc[q][2] + bv, acc[q][3] + bv);
            *(float4*)&g_xc[((size_t)n * CB_ + o) * HWS + hw0 + pb] = v;
        }
    }
}

// ---------------- gather patches into linear (n,c,i,j,wy,wx); zero means ----------------
__global__ void gather_k(int nw, int s, int k, int Btot, int tot) {
    int tid = blockIdx.x * blockDim.x + threadIdx.x;
    if (tid < tot) {
        int t = tid;
        int wx = t % nw; t /= nw;
        int wy = t % nw; t /= nw;
        int j  = t % k;  t /= k;
        int i  = t % k;  t /= k;
        int c  = t & 63;
        int n  = t >> 6;
        int h = wy * s + i, w = wx * s + j;
        g_u4[tid] = g_xc[((size_t)n * CB_ + c) * HWS + h * WW + w];
    }
    if (tid < Btot * 64) g_mean[tid] = 0.f;
}

// ---------------- conv2: per-b 64x64 conv1x1 + bias + per-(b,o) sum for mean ----------------
__global__ __launch_bounds__(288) void conv2_k(const float* __restrict__ w2,
                                               const float* __restrict__ b2,
                                               int kk, int TP, int Tq) {
    __shared__ float wT[16][64];
    __shared__ float inT[16][144];
    __shared__ float smMean[64];
    int b  = blockIdx.y;
    int p0 = blockIdx.x * TP;
    int tx = threadIdx.x;
    int T  = blockDim.x;
    int og = tx / Tq, pg = tx % Tq;
    int ob = og * 8, pb = pg * 4;
    size_t base = (size_t)b * 64 * kk;
    float acc[8][4];
#pragma unroll
    for (int i = 0; i < 8; i++)
#pragma unroll
        for (int j = 0; j < 4; j++) acc[i][j] = 0.f;

    for (int c0 = 0; c0 < 64; c0 += 16) {
        for (int e = tx; e < 1024; e += T)
            wT[e >> 6][e & 63] = w2[(e & 63) * 64 + c0 + (e >> 6)];
        for (int e = tx; e < 16 * TP; e += T) {
            int cc = e / TP, pp = e % TP;
            int p = p0 + pp;
            inT[cc][pp] = (p < kk) ? g_u4[base + (size_t)(c0 + cc) * kk + p] : 0.f;
        }
        __syncthreads();
#pragma unroll
        for (int cc = 0; cc < 16; cc++) {
            float4 iv = *(const float4*)&inT[cc][pb];
#pragma unroll
            for (int q = 0; q < 8; q++) {
                float wv = wT[cc][ob + q];
                acc[q][0] += wv * iv.x; acc[q][1] += wv * iv.y;
                acc[q][2] += wv * iv.z; acc[q][3] += wv * iv.w;
            }
        }
        __syncthreads();
    }

    if (tx < 64) smMean[tx] = 0.f;
    __syncthreads();

    int p = p0 + pb;
    bool vec_ok = ((kk & 3) == 0);
#pragma unroll
    for (int q = 0; q < 8; q++) {
        int o = ob + q;
        float bv = b2[o];
        float v0 = acc[q][0] + bv, v1 = acc[q][1] + bv,
              v2 = acc[q][2] + bv, v3 = acc[q][3] + bv;
        float psum = 0.f;
        size_t ybase = base + (size_t)o * kk + p;
        if (vec_ok && p + 3 < kk) {
            *(float4*)&g_y[ybase] = make_float4(v0, v1, v2, v3);
            psum = v0 + v1 + v2 + v3;
        } else {
            float vv[4] = {v0, v1, v2, v3};
            for (int t2 = 0; t2 < 4; t2++)
                if (p + t2 < kk) { g_y[ybase + t2] = vv[t2]; psum += vv[t2]; }
        }
        atomicAdd(&smMean[o], psum);
    }
    __syncthreads();
    if (tx < 64) atomicAdd(&g_mean[b * 64 + tx], smMean[tx]);
}

// ---------------- SE: per-b squeeze-excite scales ----------------
__global__ void se_k(const float* __restrict__ wse1,
                     const float* __restrict__ wse2, float inv_kk) {
    __shared__ float m[64];
    __shared__ float hsh[4];
    int b = blockIdx.x, c = threadIdx.x;
    m[c] = g_mean[b * 64 + c] * inv_kk;
    __syncthreads();
    if (c < 4) {
        float h = 0.f;
#pragma unroll
        for (int j = 0; j < 64; j++) h += wse1[c * 64 + j] * m[j];
        hsh[c] = fmaxf(h, 0.f);
    }
    __syncthreads();
    float sv = 0.f;
#pragma unroll
    for (int j = 0; j < 4; j++) sv += wse2[c * 4 + j] * hsh[j];
    g_scale[b * 64 + c] = 1.f / (1.f + expf(-sv));
}

// ---------------- combine: a = y*scale + dwconv3x3(u4) + bpos ----------------
__global__ __launch_bounds__(128) void comb_k(const float* __restrict__ wpos,
                                              const float* __restrict__ bpos,
                                              int k, int kk) {
    __shared__ float pl[640];
    int b = blockIdx.x, c = blockIdx.y;
    int tx = threadIdx.x;
    size_t base = ((size_t)b * 64 + c) * kk;
    for (int e = tx; e < kk; e += 128) pl[e] = g_u4[base + e];
    float wp[9];
#pragma unroll
    for (int t = 0; t < 9; t++) wp[t] = wpos[c * 9 + t];
    float sc = g_scale[b * 64 + c], bp = bpos[c];
    __syncthreads();
    for (int e = tx; e < kk; e += 128) {
        int i = e / k, j = e - i * k;
        float dw = 0.f;
#pragma unroll
        for (int di = -1; di <= 1; di++) {
            int ii = i + di;
            if (ii < 0 || ii >= k) continue;
#pragma unroll
            for (int dj = -1; dj <= 1; dj++) {
                int jj = j + dj;
                if (jj < 0 || jj >= k) continue;
                dw += wp[(di + 1) * 3 + dj + 1] * pl[ii * k + jj];
            }
        }
        g_a[base + e] = g_y[base + e] * sc + dw + bp;
    }
}

// ---------------- fold: gather overlapping window contributions, divide by count ----------------
__global__ void fold_k(int nw, int s, int k, int bi) {
    int tid = blockIdx.x * blockDim.x + threadIdx.x;
    if (tid >= N_ * CB_ * HWS) return;
    int w = tid % WW; int t = tid / WW;
    int h = t % HH; t /= HH;
    int c = t & 63;
    int n = t >> 6;
    int wy1 = min(h / s, nw - 1);
    int wy0 = wy1;
    if (wy1 > 0 && (h - (wy1 - 1) * s) < k) wy0 = wy1 - 1;
    int wx1 = min(w / s, nw - 1);
    int wx0 = wx1;
    if (wx1 > 0 && (w - (wx1 - 1) * s) < k) wx0 = wx1 - 1;
    float sum = 0.f;
    for (int wy = wy0; wy <= wy1; wy++) {
        int i = h - wy * s;
        for (int wx = wx0; wx <= wx1; wx++) {
            int j = w - wx * s;
            sum += g_a[(((((size_t)n * 64 + c) * k + i) * k + j) * nw + wy) * nw + wx];
        }
    }
    float cnt = (float)((wy1 - wy0 + 1) * (wx1 - wx0 + 1));
    g_cat[((size_t)n * CIN + bi * 64 + c) * HWS + h * WW + w] = sum / cnt;
}

// ---------------- conv3: (cat + x) @ w3(192,192) -> out ----------------
__global__ __launch_bounds__(256) void conv3_k(const float* __restrict__ x,
                                               const float* __restrict__ w3,
                                               const float* __restrict__ b3,
                                               float* __restrict__ out) {
    __shared__ float wT[16][192];
    __shared__ float inT[16][64];
    int n = blockIdx.y;
    int hw0 = blockIdx.x * 64;
    int tx = threadIdx.x;
    int og = tx >> 4, pg = tx & 15;
    int ob = og * 12, pb = pg * 4;
    float acc[12][4];
#pragma unroll
    for (int i = 0; i < 12; i++)
#pragma unroll
        for (int j = 0; j < 4; j++) acc[i][j] = 0.f;

    for (int c0 = 0; c0 < 192; c0 += 16) {
#pragma unroll
        for (int r = 0; r < 12; r++) {
            int e = tx + r * 256;
            int cc = e / 192, o = e - cc * 192;
            wT[cc][o] = w3[o * 192 + c0 + cc];
        }
#pragma unroll
        for (int r = 0; r < 4; r++) {
            int e = tx + r * 256;
            int cc = e >> 6, pp = e & 63;
            int hw = hw0 + pp;
            float v = 0.f;
            if (hw < HWS) {
                size_t idx = ((size_t)n * CIN + c0 + cc) * HWS + hw;
                v = g_cat[idx] + x[idx];
            }
            inT[cc][pp] = v;
        }
        __syncthreads();
#pragma unroll
        for (int cc = 0; cc < 16; cc++) {
            float4 iv = *(const float4*)&inT[cc][pb];
#pragma unroll
            for (int q = 0; q < 12; q++) {
                float wv = wT[cc][ob + q];
                acc[q][0] += wv * iv.x; acc[q][1] += wv * iv.y;
                acc[q][2] += wv * iv.z; acc[q][3] += wv * iv.w;
            }
        }
        __syncthreads();
    }
    if (hw0 + pb < HWS) {
#pragma unroll
        for (int q = 0; q < 12; q++) {
            int o = ob + q;
            float bv = b3[o];
            *(float4*)&out[((size_t)n * CIN + o) * HWS + hw0 + pb] =
                make_float4(acc[q][0] + bv, acc[q][1] + bv, acc[q][2] + bv, acc[q][3] + bv);
        }
    }
}

extern "C" void kernel_launch(void* const* d_in, const int* in_sizes, int n_in,
                              void* d_out, int out_size) {
    const float* x    = (const float*)d_in[0];
    const float* w1   = (const float*)d_in[1];
    const float* b1   = (const float*)d_in[2];
    const float* w2   = (const float*)d_in[3];
    const float* b2   = (const float*)d_in[4];
    const float* w3   = (const float*)d_in[5];
    const float* b3   = (const float*)d_in[6];
    const float* wpos = (const float*)d_in[7];
    const float* bpos = (const float*)d_in[8];
    const float* wse1 = (const float*)d_in[9];
    const float* wse2 = (const float*)d_in[10];
    float* out = (float*)d_out;

    conv1_k<<<dim3(79, 16), 256>>>(x, w1, b1);

    const int NWs[3] = {4, 8, 12};
    const int Ss[3]  = {25, 12, 8};
    const int Ks[3]  = {25, 16, 12};
    for (int bi = 0; bi < 3; bi++) {
        int nw = NWs[bi], s = Ss[bi], k = Ks[bi];
        int kk = k * k;
        int Btot = N_ * nw * nw;
        int tot = N_ * CB_ * kk * nw * nw;

        gather_k<<<(tot + 255) / 256, 256>>>(nw, s, k, Btot, tot);

        int TP = (bi == 2) ? 144 : 128;   // exact tile for kk=144; 128 otherwise
        int Tq = TP / 4;
        conv2_k<<<dim3((kk + TP - 1) / TP, Btot), 2 * TP>>>(w2, b2, kk, TP, Tq);

        se_k<<<Btot, 64>>>(wse1, wse2, 1.0f / (float)kk);

        comb_k<<<dim3(Btot, 64), 128>>>(wpos, bpos, k, kk);

        fold_k<<<(N_ * CB_ * HWS + 255) / 256, 256>>>(nw, s, k, bi);
    }

    conv3_k<<<dim3(157, 16), 256>>>(x, w3, b3, out);
}

// round 7
// speedup vs baseline: 1.0668x; 1.0668x over previous
#include <cuda_runtime.h>
#include <math.h>

#define N_   16
#define CIN  192
#define CB_  64
#define HH   100
#define WW   100
#define HWS  10000

// Max branch (nw=12, k=12): 16*64*(12*12)^2 = 21,233,664 elems
#define MAXEL (16*64*20736)

__device__ float g_xc [N_*CB_*HWS];     // conv1 output (16,64,100,100)
__device__ float g_y  [MAXEL];          // conv2 output (u4-view layout)
__device__ float g_a  [MAXEL];          // se*y + dwconv + bpos
__device__ float g_cat[N_*CIN*HWS];     // folded concat (16,192,100,100)
// per-branch offsets {0,256,1280}, total 3584 batches x 64 ch
__device__ float g_mean [3584*64];
__device__ float g_scale[3584*64];

// packed dual fp32 FMA (sm_103a FFMA2) — exact fp32 semantics per lane
__device__ __forceinline__ unsigned long long ffma2(unsigned long long a,
                                                    unsigned long long b,
                                                    unsigned long long c) {
    unsigned long long d;
    asm("fma.rn.f32x2 %0, %1, %2, %3;" : "=l"(d) : "l"(a), "l"(b), "l"(c));
    return d;
}
__device__ __forceinline__ float2 unpack2(unsigned long long v) {
    float2 r;
    asm("mov.b64 {%0, %1}, %2;" : "=f"(r.x), "=f"(r.y) : "l"(v));
    return r;
}

// u4 linear offset o (layout (n,c,i,j,wy,wx)) -> value, read straight from g_xc.
// All divisors are compile-time constants -> mul/shift.
template<int NW, int S, int K>
__device__ __forceinline__ float load_u4(int o) {
    int wx = o % NW; o /= NW;
    int wy = o % NW; o /= NW;
    int j  = o % K;  o /= K;
    int i  = o % K;  o /= K;
    int c  = o & 63;
    int n  = o >> 6;
    return g_xc[((size_t)(n * 64 + c)) * HWS + (wy * S + i) * WW + (wx * S + j)];
}

// ---------------- conv1: x(16,192,100,100) @ w1(64,192) -> g_xc; zero g_mean ----------------
__global__ __launch_bounds__(256) void conv1_k(const float* __restrict__ x,
                                               const float* __restrict__ w1,
                                               const float* __restrict__ b1) {
    __shared__ __align__(16) float2 wP[16][64];
    __shared__ __align__(16) float  inT[16][128];
    int n = blockIdx.y;
    int hw0 = blockIdx.x * 128;
    int tx = threadIdx.x;
    // zero the mean accumulators for all three branches (runs before any conv2)
    int gid = (blockIdx.y * gridDim.x + blockIdx.x) * 256 + tx;
    if (gid < 3584 * 64) g_mean[gid] = 0.f;

    int og = tx >> 5, pg = tx & 31;
    int ob = og * 8, pb = pg * 4;
    unsigned long long acc[8][2];
#pragma unroll
    for (int i = 0; i < 8; i++) { acc[i][0] = 0ull; acc[i][1] = 0ull; }

    for (int c0 = 0; c0 < 192; c0 += 16) {
#pragma unroll
        for (int r = 0; r < 4; r++) {
            int e = tx + r * 256;
            float wv = w1[(e & 63) * 192 + c0 + (e >> 6)];
            wP[e >> 6][e & 63] = make_float2(wv, wv);
        }
#pragma unroll
        for (int r = 0; r < 8; r++) {
            int e = tx + r * 256;
            int cc = e >> 7, pp = e & 127;
            int hw = hw0 + pp;
            inT[cc][pp] = (hw < HWS) ? x[((size_t)n * CIN + c0 + cc) * HWS + hw] : 0.f;
        }
        __syncthreads();
#pragma unroll
        for (int cc = 0; cc < 16; cc++) {
            ulonglong2 iv = *(const ulonglong2*)&inT[cc][pb];
#pragma unroll
            for (int q = 0; q < 8; q++) {
                unsigned long long wv = *(const unsigned long long*)&wP[cc][ob + q];
                acc[q][0] = ffma2(wv, iv.x, acc[q][0]);
                acc[q][1] = ffma2(wv, iv.y, acc[q][1]);
            }
        }
        __syncthreads();
    }
    if (hw0 + pb < HWS) {
#pragma unroll
        for (int q = 0; q < 8; q++) {
            int o = ob + q;
            float bv = b1[o];
            float2 v0 = unpack2(acc[q][0]), v1 = unpack2(acc[q][1]);
            *(float4*)&g_xc[((size_t)n * CB_ + o) * HWS + hw0 + pb] =
                make_float4(v0.x + bv, v0.y + bv, v1.x + bv, v1.y + bv);
        }
    }
}

// ---------------- conv2: per-b 64x64 conv1x1 + bias + per-(b,o) sum for mean ----------------
// Input gathered directly from g_xc (u4 never materialized).
template<int NW, int S, int K, int TP>
__global__ __launch_bounds__(2 * TP) void conv2_k(const float* __restrict__ w2,
                                                  const float* __restrict__ b2,
                                                  int mean_off) {
    constexpr int KK = K * K;
    constexpr int Tq = TP / 4;
    __shared__ __align__(16) float2 wP[16][64];
    __shared__ __align__(16) float  inT[16][TP];
    __shared__ float smMean[64];
    int b  = blockIdx.y;
    int p0 = blockIdx.x * TP;
    int tx = threadIdx.x;
    constexpr int T = 2 * TP;
    int og = tx / Tq, pg = tx % Tq;
    int ob = og * 8, pb = pg * 4;
    int base = b * 64 * KK;
    unsigned long long acc[8][2];
#pragma unroll
    for (int i = 0; i < 8; i++) { acc[i][0] = 0ull; acc[i][1] = 0ull; }

    for (int c0 = 0; c0 < 64; c0 += 16) {
#pragma unroll
        for (int e = tx; e < 1024; e += T) {
            float wv = w2[(e & 63) * 64 + c0 + (e >> 6)];
            wP[e >> 6][e & 63] = make_float2(wv, wv);
        }
#pragma unroll
        for (int e = tx; e < 16 * TP; e += T) {
            int cc = e / TP, pp = e % TP;
            int p = p0 + pp;
            inT[cc][pp] = (p < KK) ? load_u4<NW, S, K>(base + (c0 + cc) * KK + p) : 0.f;
        }
        __syncthreads();
#pragma unroll
        for (int cc = 0; cc < 16; cc++) {
            ulonglong2 iv = *(const ulonglong2*)&inT[cc][pb];
#pragma unroll
            for (int q = 0; q < 8; q++) {
                unsigned long long wv = *(const unsigned long long*)&wP[cc][ob + q];
                acc[q][0] = ffma2(wv, iv.x, acc[q][0]);
                acc[q][1] = ffma2(wv, iv.y, acc[q][1]);
            }
        }
        __syncthreads();
    }

    if (tx < 64) smMean[tx] = 0.f;
    __syncthreads();

    int p = p0 + pb;
#pragma unroll
    for (int q = 0; q < 8; q++) {
        int o = ob + q;
        float bv = b2[o];
        float2 a0 = unpack2(acc[q][0]), a1 = unpack2(acc[q][1]);
        float v0 = a0.x + bv, v1 = a0.y + bv, v2 = a1.x + bv, v3 = a1.y + bv;
        float psum = 0.f;
        size_t ybase = (size_t)base + (size_t)o * KK + p;
        if ((KK % 4 == 0) && p + 3 < KK) {
            *(float4*)&g_y[ybase] = make_float4(v0, v1, v2, v3);
            psum = v0 + v1 + v2 + v3;
        } else {
            float vv[4] = {v0, v1, v2, v3};
            for (int t2 = 0; t2 < 4; t2++)
                if (p + t2 < KK) { g_y[ybase + t2] = vv[t2]; psum += vv[t2]; }
        }
        atomicAdd(&smMean[o], psum);
    }
    __syncthreads();
    if (tx < 64) atomicAdd(&g_mean[(mean_off + b) * 64 + tx], smMean[tx]);
}

// ---------------- SE: per-b squeeze-excite scales ----------------
__global__ void se_k(const float* __restrict__ wse1,
                     const float* __restrict__ wse2, float inv_kk, int mean_off) {
    __shared__ float m[64];
    __shared__ float hsh[4];
    int b = blockIdx.x + mean_off, c = threadIdx.x;
    m[c] = g_mean[b * 64 + c] * inv_kk;
    __syncthreads();
    if (c < 4) {
        float h = 0.f;
#pragma unroll
        for (int j = 0; j < 64; j++) h += wse1[c * 64 + j] * m[j];
        hsh[c] = fmaxf(h, 0.f);
    }
    __syncthreads();
    float sv = 0.f;
#pragma unroll
    for (int j = 0; j < 4; j++) sv += wse2[c * 4 + j] * hsh[j];
    g_scale[b * 64 + c] = 1.f / (1.f + expf(-sv));
}

// ---------------- combine: a = y*scale + dwconv3x3(u4) + bpos ----------------
template<int NW, int S, int K>
__global__ __launch_bounds__(128) void comb_k(const float* __restrict__ wpos,
                                              const float* __restrict__ bpos,
                                              int mean_off) {
    constexpr int KK = K * K;
    __shared__ float pl[KK];
    int b = blockIdx.x, c = blockIdx.y;
    int tx = threadIdx.x;
    int base = (b * 64 + c) * KK;
    for (int e = tx; e < KK; e += 128) pl[e] = load_u4<NW, S, K>(base + e);
    float wp[9];
#pragma unroll
    for (int t = 0; t < 9; t++) wp[t] = wpos[c * 9 + t];
    float sc = g_scale[(mean_off + b) * 64 + c], bp = bpos[c];
    __syncthreads();
    for (int e = tx; e < KK; e += 128) {
        int i = e / K, j = e - i * K;
        float dw = 0.f;
#pragma unroll
        for (int di = -1; di <= 1; di++) {
            int ii = i + di;
            if (ii < 0 || ii >= K) continue;
#pragma unroll
            for (int dj = -1; dj <= 1; dj++) {
                int jj = j + dj;
                if (jj < 0 || jj >= K) continue;
                dw += wp[(di + 1) * 3 + dj + 1] * pl[ii * K + jj];
            }
        }
        g_a[base + e] = g_y[base + e] * sc + dw + bp;
    }
}

// ---------------- fold: gather overlapping window contributions, divide by count ----------------
template<int NW, int S, int K>
__global__ void fold_k(int bi) {
    int tid = blockIdx.x * blockDim.x + threadIdx.x;
    if (tid >= N_ * CB_ * HWS) return;
    int w = tid % WW; int t = tid / WW;
    int h = t % HH; t /= HH;
    int c = t & 63;
    int n = t >> 6;
    int wy1 = min(h / S, NW - 1);
    int wy0 = wy1;
    if (wy1 > 0 && (h - (wy1 - 1) * S) < K) wy0 = wy1 - 1;
    int wx1 = min(w / S, NW - 1);
    int wx0 = wx1;
    if (wx1 > 0 && (w - (wx1 - 1) * S) < K) wx0 = wx1 - 1;
    float sum = 0.f;
    for (int wy = wy0; wy <= wy1; wy++) {
        int i = h - wy * S;
        for (int wx = wx0; wx <= wx1; wx++) {
            int j = w - wx * S;
            sum += g_a[((((n * 64 + c) * K + i) * K + j) * NW + wy) * NW + wx];
        }
    }
    float cnt = (float)((wy1 - wy0 + 1) * (wx1 - wx0 + 1));
    g_cat[((size_t)n * CIN + bi * 64 + c) * HWS + h * WW + w] = sum / cnt;
}

// ---------------- conv3: (cat + x) @ w3(192,192) -> out ----------------
__global__ __launch_bounds__(256) void conv3_k(const float* __restrict__ x,
                                               const float* __restrict__ w3,
                                               const float* __restrict__ b3,
                                               float* __restrict__ out) {
    __shared__ __align__(16) float2 wP[16][192];
    __shared__ __align__(16) float  inT[16][64];
    int n = blockIdx.y;
    int hw0 = blockIdx.x * 64;
    int tx = threadIdx.x;
    int og = tx >> 4, pg = tx & 15;
    int ob = og * 12, pb = pg * 4;
    unsigned long long acc[12][2];
#pragma unroll
    for (int i = 0; i < 12; i++) { acc[i][0] = 0ull; acc[i][1] = 0ull; }

    for (int c0 = 0; c0 < 192; c0 += 16) {
#pragma unroll
        for (int r = 0; r < 12; r++) {
            int e = tx + r * 256;
            int cc = e / 192, o = e - cc * 192;
            float wv = w3[o * 192 + c0 + cc];
            wP[cc][o] = make_float2(wv, wv);
        }
#pragma unroll
        for (int r = 0; r < 4; r++) {
            int e = tx + r * 256;
            int cc = e >> 6, pp = e & 63;
            int hw = hw0 + pp;
            float v = 0.f;
            if (hw < HWS) {
                size_t idx = ((size_t)n * CIN + c0 + cc) * HWS + hw;
                v = g_cat[idx] + x[idx];
            }
            inT[cc][pp] = v;
        }
        __syncthreads();
#pragma unroll
        for (int cc = 0; cc < 16; cc++) {
            ulonglong2 iv = *(const ulonglong2*)&inT[cc][pb];
#pragma unroll
            for (int q = 0; q < 12; q++) {
                unsigned long long wv = *(const unsigned long long*)&wP[cc][ob + q];
                acc[q][0] = ffma2(wv, iv.x, acc[q][0]);
                acc[q][1] = ffma2(wv, iv.y, acc[q][1]);
            }
        }
        __syncthreads();
    }
    if (hw0 + pb < HWS) {
#pragma unroll
        for (int q = 0; q < 12; q++) {
            int o = ob + q;
            float bv = b3[o];
            float2 v0 = unpack2(acc[q][0]), v1 = unpack2(acc[q][1]);
            *(float4*)&out[((size_t)n * CIN + o) * HWS + hw0 + pb] =
                make_float4(v0.x + bv, v0.y + bv, v1.x + bv, v1.y + bv);
        }
    }
}

template<int NW, int S, int K, int TP>
static void run_branch(int bi, int mean_off,
                       const float* w2, const float* b2,
                       const float* wse1, const float* wse2,
                       const float* wpos, const float* bpos) {
    constexpr int KK = K * K;
    constexpr int Btot = N_ * NW * NW;
    conv2_k<NW, S, K, TP><<<dim3((KK + TP - 1) / TP, Btot), 2 * TP>>>(w2, b2, mean_off);
    se_k<<<Btot, 64>>>(wse1, wse2, 1.0f / (float)KK, mean_off);
    comb_k<NW, S, K><<<dim3(Btot, 64), 128>>>(wpos, bpos, mean_off);
    fold_k<NW, S, K><<<(N_ * CB_ * HWS + 255) / 256, 256>>>(bi);
}

extern "C" void kernel_launch(void* const* d_in, const int* in_sizes, int n_in,
                              void* d_out, int out_size) {
    const float* x    = (const float*)d_in[0];
    const float* w1   = (const float*)d_in[1];
    const float* b1   = (const float*)d_in[2];
    const float* w2   = (const float*)d_in[3];
    const float* b2   = (const float*)d_in[4];
    const float* w3   = (const float*)d_in[5];
    const float* b3   = (const float*)d_in[6];
    const float* wpos = (const float*)d_in[7];
    const float* bpos = (const float*)d_in[8];
    const float* wse1 = (const float*)d_in[9];
    const float* wse2 = (const float*)d_in[10];
    float* out = (float*)d_out;

    conv1_k<<<dim3(79, 16), 256>>>(x, w1, b1);

    run_branch<4, 25, 25, 128>(0, 0,    w2, b2, wse1, wse2, wpos, bpos);
    run_branch<8, 12, 16, 128>(1, 256,  w2, b2, wse1, wse2, wpos, bpos);
    run_branch<12, 8, 12, 144>(2, 1280, w2, b2, wse1, wse2, wpos, bpos);

    conv3_k<<<dim3(157, 16), 256>>>(x, w3, b3, out);
}